// round 11
// baseline (speedup 1.0000x reference)
#include <cuda_runtime.h>
#include <cstdint>

// ---------------------------------------------------------------------------
// NNUE forward, TF32-faithful, target sm_100 (mma.sync tensor path).
//   memset:    zero per-position feature counters
//   scan:      OR-accumulate register-resident scan of white/black multihot
//   transpose: Ww/Wb (256 x 40960) -> (40960 x 256), tf32-rounded
//   round_all: Wm0/Wm1/W0/W1/W2 -> tf32-rounded scratch (one launch)
//   gather:    cp.async double-buffered row staging + sum -> base[B,512];
//              fused value head. One block per position.
//   gemm_mma:  mma.sync m16n8k8 tf32, 128x128 CTA tile, cp.async 2-stage
// ---------------------------------------------------------------------------

#define HALF_KP 40960
#define HALF_KP4 (HALF_KP / 4)
#define MOVE_N  4096
#define BATCH_MAX 4096

// +1 row: row HALF_KP is a permanent zero row (never written; __device__
// globals are zero-initialized) used to pad variable-length gathers.
__device__ float g_WwT[(size_t)(HALF_KP + 1) * 256];
__device__ float g_WbT[(size_t)(HALF_KP + 1) * 256];
__device__ float g_base[BATCH_MAX * 512];
__device__ float g_hidden[BATCH_MAX * 256];
__device__ float g_Wm0r[256 * 512];
__device__ float g_Wm1r[(size_t)MOVE_N * 256];
__device__ float g_W0r[32 * 512];
__device__ float g_W1r[32 * 32];
__device__ float g_W2r[32];
__device__ int   g_cnt[2 * BATCH_MAX];
__device__ int   g_idx[2 * BATCH_MAX * 64];

__device__ __forceinline__ float tf32r(float x) {
    uint32_t u;
    asm("cvt.rna.tf32.f32 %0, %1;" : "=r"(u) : "f"(x));
    return __uint_as_float(u);
}

__device__ __forceinline__ uint32_t smem_to_u32(const void* p) {
    uint32_t a;
    asm("{ .reg .u64 t; cvta.to.shared.u64 t, %1; cvt.u32.u64 %0, t; }"
        : "=r"(a) : "l"(p));
    return a;
}

__device__ __forceinline__ void cp16(uint32_t dst, const void* src) {
    asm volatile("cp.async.cg.shared.global [%0], [%1], 16;"
                 :: "r"(dst), "l"(src) : "memory");
}

// ---------------------------------------------------------------------------
// All weight rounding in one launch. float4 ranges.
// ---------------------------------------------------------------------------
__global__ __launch_bounds__(256) void round_all_kernel(
    const float* __restrict__ Wm0, float* __restrict__ Wm0r,
    const float* __restrict__ Wm1, float* __restrict__ Wm1r,
    const float* __restrict__ W0,  float* __restrict__ W0r,
    const float* __restrict__ W1,  float* __restrict__ W1r,
    const float* __restrict__ W2,  float* __restrict__ W2r)
{
    constexpr int nA = 256 * 512 / 4;
    constexpr int nB = MOVE_N * 256 / 4;
    constexpr int nC = 32 * 512 / 4;
    constexpr int nD = 32 * 32 / 4;
    constexpr int nE = 32 / 4;
    constexpr int total = nA + nB + nC + nD + nE;

    for (int i = blockIdx.x * 256 + threadIdx.x; i < total;
         i += gridDim.x * 256) {
        const float4* src;
        float4* dst;
        int j = i;
        if (j < nA)              { src = (const float4*)Wm0; dst = (float4*)Wm0r; }
        else if ((j -= nA) < nB) { src = (const float4*)Wm1; dst = (float4*)Wm1r; }
        else if ((j -= nB) < nC) { src = (const float4*)W0;  dst = (float4*)W0r;  }
        else if ((j -= nC) < nD) { src = (const float4*)W1;  dst = (float4*)W1r;  }
        else { j -= nD;            src = (const float4*)W2;  dst = (float4*)W2r;  }
        float4 v = src[j];
        float4 w;
        w.x = tf32r(v.x); w.y = tf32r(v.y); w.z = tf32r(v.z); w.w = tf32r(v.w);
        dst[j] = w;
    }
}

// ---------------------------------------------------------------------------
// Fused transpose of both tables: [256, HALF_KP] -> [HALF_KP, 256], tf32.
// Never touches row HALF_KP of the destination (the zero row).
// ---------------------------------------------------------------------------
__global__ __launch_bounds__(256) void transpose_kernel(
    const float* __restrict__ srcW, float* __restrict__ dstW,
    const float* __restrict__ srcB, float* __restrict__ dstB)
{
    __shared__ float tile[32][33];
    const float* src = blockIdx.z ? srcB : srcW;
    float*       dst = blockIdx.z ? dstB : dstW;
    const int f0 = blockIdx.x * 32;
    const int o0 = blockIdx.y * 32;
    const int tx = threadIdx.x;
    const int ty = threadIdx.y;
    #pragma unroll
    for (int i = 0; i < 32; i += 8)
        tile[ty + i][tx] = tf32r(src[(size_t)(o0 + ty + i) * HALF_KP + f0 + tx]);
    __syncthreads();
    #pragma unroll
    for (int i = 0; i < 32; i += 8)
        dst[(size_t)(f0 + ty + i) * 256 + o0 + tx] = tile[tx][ty + i];
}

// ---------------------------------------------------------------------------
// Scan: warp-cooperative 4KB chunks, register-resident OR-accumulate test.
// ---------------------------------------------------------------------------
__device__ __forceinline__ void scan_chunk(
    const uint4* __restrict__ arr, int base, int lane, int side)
{
    uint4 v[8];
    #pragma unroll
    for (int k = 0; k < 8; k++)
        v[k] = __ldcs(arr + base + k * 32 + lane);
    uint32_t a0 = 0, a1 = 0;
    #pragma unroll
    for (int k = 0; k < 8; k++) {
        a0 |= v[k].x | v[k].y;
        a1 |= v[k].z | v[k].w;
    }
    if (a0 | a1) {
        const int pos   = base / HALF_KP4;
        const int fbase = (base - pos * HALF_KP4) * 4;
        int* cnt = &g_cnt[side + pos];
        int* idx = &g_idx[(size_t)(side + pos) * 64];
        #pragma unroll
        for (int k = 0; k < 8; k++) {
            if (v[k].x | v[k].y | v[k].z | v[k].w) {
                const int f0 = fbase + (k * 32 + lane) * 4;
                if (v[k].x) { int p = atomicAdd(cnt, 1); if (p < 64) idx[p] = f0;     }
                if (v[k].y) { int p = atomicAdd(cnt, 1); if (p < 64) idx[p] = f0 + 1; }
                if (v[k].z) { int p = atomicAdd(cnt, 1); if (p < 64) idx[p] = f0 + 2; }
                if (v[k].w) { int p = atomicAdd(cnt, 1); if (p < 64) idx[p] = f0 + 3; }
            }
        }
    }
}

__global__ __launch_bounds__(256) void scan_kernel(
    const uint4* __restrict__ white, const uint4* __restrict__ black,
    int nchunks)
{
    const int lane  = threadIdx.x & 31;
    const int warp0 = blockIdx.x * 8 + (threadIdx.x >> 5);
    const int nwarp = gridDim.x * 8;
    for (int c = warp0; c < nchunks; c += nwarp) {
        const int base = c * 256;
        scan_chunk(white, base, lane, 0);
        scan_chunk(black, base, lane, BATCH_MAX);
    }
}

// ---------------------------------------------------------------------------
// Gather via cp.async staging: rows streamed into smem in 8-row chunks
// (double-buffered), summed from smem. Then pov select + value head.
// One block per position, 256 threads. All float4/cp.async smem 16B-aligned.
// ---------------------------------------------------------------------------
#define CH_ROWS   8
#define ROW_F     260                       // 256 floats + 4 pad (1040 B)
#define BUF_F     (CH_ROWS * ROW_F)         // floats per buffer

__global__ __launch_bounds__(256) void gather_kernel(
    const float* __restrict__ pov,
    const float* __restrict__ WwT, const float* __restrict__ bw,
    const float* __restrict__ WbT, const float* __restrict__ bb,
    const float* __restrict__ W0r, const float* __restrict__ b0,
    const float* __restrict__ W1r, const float* __restrict__ b1,
    const float* __restrict__ W2r, const float* __restrict__ b2,
    float* __restrict__ xout)
{
    const int b = blockIdx.x;
    const int t = threadIdx.x;
    const int col = t & 63;                  // float4 column 0..63
    const int grp = t >> 6;                  // row group 0..3

    __shared__ int   sIdx[128];              // [0:64) white, [64:128) black
    __shared__ int   sn[2];
    __shared__ __align__(16) float sBuf[2][BUF_F];   // staging, double buffer
    __shared__ __align__(16) float sPartW[4][256];
    __shared__ __align__(16) float sPartB[4][256];
    __shared__ __align__(16) float sbase[512];
    __shared__ float h0[32], h1[32];

    if (t < 2) sn[t] = min(g_cnt[t * BATCH_MAX + b], 64);
    if (t < 64)       sIdx[t] = g_idx[b * 64 + t];
    else if (t < 128) sIdx[t] = g_idx[(size_t)(BATCH_MAX + b) * 64 + (t - 64)];
    __syncthreads();

    const int nW = sn[0];
    const int nB = sn[1];
    // pad with zero-row index
    if (t < 64 && t >= nW)                         sIdx[t] = HALF_KP;
    else if (t >= 64 && t < 128 && (t - 64) >= nB) sIdx[t] = HALF_KP;
    __syncthreads();

    const int ncW = (nW + CH_ROWS - 1) / CH_ROWS;
    const int ncB = (nB + CH_ROWS - 1) / CH_ROWS;
    const int nc  = ncW + ncB;

    const uint32_t sbuf0 = smem_to_u32(&sBuf[0][0]);

    // issue chunk c into buffer (c&1). Each thread: 2 cp16 (rows grp, grp+4).
    auto issue = [&](int c) {
        const int  sideB = (c >= ncW);
        const int  lc    = sideB ? (c - ncW) : c;
        const float* T   = sideB ? WbT : WwT;
        const int* idx   = sIdx + (sideB ? 64 : 0) + lc * CH_ROWS;
        const uint32_t bufb = sbuf0 + (uint32_t)(c & 1) * (BUF_F * 4);
        #pragma unroll
        for (int rr = 0; rr < 2; rr++) {
            const int row = grp + rr * 4;
            cp16(bufb + (uint32_t)(row * ROW_F + col * 4) * 4,
                 T + (size_t)idx[row] * 256 + col * 4);
        }
        asm volatile("cp.async.commit_group;" ::: "memory");
    };

    float4 accW = {0.f, 0.f, 0.f, 0.f};
    float4 accB = {0.f, 0.f, 0.f, 0.f};

    if (nc > 0) issue(0);
    for (int c = 0; c < nc; c++) {
        if (c + 1 < nc) {
            issue(c + 1);
            asm volatile("cp.async.wait_group 1;" ::: "memory");
        } else {
            asm volatile("cp.async.wait_group 0;" ::: "memory");
        }
        __syncthreads();
        const float* buf = &sBuf[c & 1][0];
        const float4 v0 = *(const float4*)(buf + (grp)     * ROW_F + col * 4);
        const float4 v1 = *(const float4*)(buf + (grp + 4) * ROW_F + col * 4);
        if (c >= ncW) {
            accB.x += v0.x + v1.x; accB.y += v0.y + v1.y;
            accB.z += v0.z + v1.z; accB.w += v0.w + v1.w;
        } else {
            accW.x += v0.x + v1.x; accW.y += v0.y + v1.y;
            accW.z += v0.z + v1.z; accW.w += v0.w + v1.w;
        }
        __syncthreads();   // buffer reusable for issue(c+2)
    }

    *(float4*)&sPartW[grp][col * 4] = accW;
    *(float4*)&sPartB[grp][col * 4] = accB;
    __syncthreads();

    // combine partials, pov select, relu, write base
    {
        const float accw = ((sPartW[0][t] + sPartW[1][t]) +
                            (sPartW[2][t] + sPartW[3][t])) + bw[t];
        const float accb = ((sPartB[0][t] + sPartB[1][t]) +
                            (sPartB[2][t] + sPartB[3][t])) + bb[t];
        const bool p = (pov[b] != 0.f);
        const float r0 = tf32r(fmaxf(p ? accw : accb, 0.f));
        const float r1 = tf32r(fmaxf(p ? accb : accw, 0.f));
        sbase[t]       = r0;
        sbase[t + 256] = r1;
        float* baserow = g_base + (size_t)b * 512;
        baserow[t]       = r0;
        baserow[t + 256] = r1;
    }
    __syncthreads();

    // value head: fc0 (32 outputs x 8 lanes, shuffle-reduce)
    {
        const int o = t >> 3;
        const int r = t & 7;
        const float4* w4 = (const float4*)(W0r + o * 512 + r * 64);
        const float4* s4 = (const float4*)(sbase + r * 64);
        float s0 = 0.f, s1 = 0.f, s2 = 0.f, s3 = 0.f;
        #pragma unroll
        for (int j = 0; j < 16; j++) {
            float4 wv = w4[j];
            float4 sv = s4[j];
            s0 += wv.x * sv.x; s1 += wv.y * sv.y;
            s2 += wv.z * sv.z; s3 += wv.w * sv.w;
        }
        float s = (s0 + s1) + (s2 + s3);
        s += __shfl_down_sync(0xffffffffu, s, 4);
        s += __shfl_down_sync(0xffffffffu, s, 2);
        s += __shfl_down_sync(0xffffffffu, s, 1);
        if (r == 0) h0[o] = tf32r(fmaxf(s + b0[o], 0.f));
    }
    __syncthreads();
    if (t < 32) {
        float s = 0.f;
        const float* w = W1r + t * 32;
        #pragma unroll
        for (int k = 0; k < 32; k++) s += w[k] * h0[k];
        h1[t] = tf32r(fmaxf(s + b1[t], 0.f));
    }
    __syncthreads();
    if (t == 0) {
        float s = 0.f;
        #pragma unroll
        for (int k = 0; k < 32; k++) s += W2r[k] * h1[k];
        xout[b] = s + b2[0];
    }
}

// ---------------------------------------------------------------------------
// TF32 mma.sync NT GEMM: C[M,N] = relu(A[M,K] @ Bm[N,K]^T + bias[N])
// 128x128 CTA tile, 8 warps, warp 64x32. K-chunk 32, 2-stage cp.async.
// ---------------------------------------------------------------------------
template <bool ROUND_OUT>
__global__ __launch_bounds__(256) void gemm_mma(
    const float* __restrict__ A,
    const float* __restrict__ Bm,
    const float* __restrict__ bias,
    float* __restrict__ C,
    int M, int N, int K)
{
    extern __shared__ float smem[];
    constexpr int TILE = 4608;
    constexpr int STAGE = 2 * TILE;

    const int tid  = threadIdx.x;
    const int wid  = tid >> 5;
    const int lane = tid & 31;
    const int q    = lane >> 2;
    const int r    = lane & 3;
    const int wm   = (wid & 1) * 64;
    const int wn   = (wid >> 1) * 32;
    const int m0   = blockIdx.y * 128;
    const int n0   = blockIdx.x * 128;

    const uint32_t sb = smem_to_u32(smem);

    float acc[4][4][4];
    #pragma unroll
    for (int i = 0; i < 4; i++)
        #pragma unroll
        for (int j = 0; j < 4; j++)
            #pragma unroll
            for (int c = 0; c < 4; c++) acc[i][j][c] = 0.f;

    const int nK = K / 32;

    auto load_chunk = [&](int kc, int stage) {
        const uint32_t aAddr = sb + stage * STAGE * 4;
        const uint32_t bAddr = aAddr + TILE * 4;
        const int k0 = kc * 32;
        #pragma unroll
        for (int i = 0; i < 4; i++) {
            int u  = i * 256 + tid;
            int rr = u >> 3;
            int c4 = u & 7;
            uint32_t off = (uint32_t)(rr * 36 + c4 * 4) * 4;
            cp16(aAddr + off, A  + (size_t)(m0 + rr) * K + k0 + c4 * 4);
            cp16(bAddr + off, Bm + (size_t)(n0 + rr) * K + k0 + c4 * 4);
        }
        asm volatile("cp.async.commit_group;" ::: "memory");
    };

    load_chunk(0, 0);

    for (int kc = 0; kc < nK; kc++) {
        const int stage = kc & 1;
        if (kc + 1 < nK) {
            load_chunk(kc + 1, stage ^ 1);
            asm volatile("cp.async.wait_group 1;" ::: "memory");
        } else {
            asm volatile("cp.async.wait_group 0;" ::: "memory");
        }
        __syncthreads();

        const float* Ab = smem + stage * STAGE;
        const float* Bb = Ab + TILE;

        #pragma unroll
        for (int ks = 0; ks < 4; ks++) {
            const int k = ks * 8;
            uint32_t a[4][4];
            #pragma unroll
            for (int i = 0; i < 4; i++) {
                const int m = wm + 16 * i + q;
                a[i][0] = __float_as_uint(Ab[m * 36 + k + r]);
                a[i][1] = __float_as_uint(Ab[(m + 8) * 36 + k + r]);
                a[i][2] = __float_as_uint(Ab[m * 36 + k + r + 4]);
                a[i][3] = __float_as_uint(Ab[(m + 8) * 36 + k + r + 4]);
            }
            uint32_t bfr[4][2];
            #pragma unroll
            for (int j = 0; j < 4; j++) {
                const int n = wn + 8 * j + q;
                bfr[j][0] = __float_as_uint(Bb[n * 36 + k + r]);
                bfr[j][1] = __float_as_uint(Bb[n * 36 + k + r + 4]);
            }
            #pragma unroll
            for (int i = 0; i < 4; i++)
                #pragma unroll
                for (int j = 0; j < 4; j++) {
                    asm volatile(
                        "mma.sync.aligned.m16n8k8.row.col.f32.tf32.tf32.f32 "
                        "{%0,%1,%2,%3}, {%4,%5,%6,%7}, {%8,%9}, {%0,%1,%2,%3};"
                        : "+f"(acc[i][j][0]), "+f"(acc[i][j][1]),
                          "+f"(acc[i][j][2]), "+f"(acc[i][j][3])
                        : "r"(a[i][0]), "r"(a[i][1]), "r"(a[i][2]), "r"(a[i][3]),
                          "r"(bfr[j][0]), "r"(bfr[j][1]));
                }
        }
        __syncthreads();
    }

    #pragma unroll
    for (int i = 0; i < 4; i++) {
        #pragma unroll
        for (int j = 0; j < 4; j++) {
            const int row = m0 + wm + 16 * i + q;
            const int col = n0 + wn + 8 * j + 2 * r;
            const float bj0 = bias[col];
            const float bj1 = bias[col + 1];
            float v00 = fmaxf(acc[i][j][0] + bj0, 0.f);
            float v01 = fmaxf(acc[i][j][1] + bj1, 0.f);
            float v10 = fmaxf(acc[i][j][2] + bj0, 0.f);
            float v11 = fmaxf(acc[i][j][3] + bj1, 0.f);
            if (ROUND_OUT) {
                v00 = tf32r(v00); v01 = tf32r(v01);
                v10 = tf32r(v10); v11 = tf32r(v11);
            }
            float2 lo = make_float2(v00, v01);
            float2 hi = make_float2(v10, v11);
            *(float2*)(C + (size_t)row * N + col)       = lo;
            *(float2*)(C + (size_t)(row + 8) * N + col) = hi;
        }
    }
}

// ---------------------------------------------------------------------------
extern "C" void kernel_launch(void* const* d_in, const int* in_sizes, int n_in,
                              void* d_out, int out_size)
{
    const float* pov   = (const float*)d_in[0];
    const float* white = (const float*)d_in[1];
    const float* black = (const float*)d_in[2];
    const float* Ww    = (const float*)d_in[3];
    const float* bw    = (const float*)d_in[4];
    const float* Wb    = (const float*)d_in[5];
    const float* bb    = (const float*)d_in[6];
    const float* W0    = (const float*)d_in[7];
    const float* b0    = (const float*)d_in[8];
    const float* W1    = (const float*)d_in[9];
    const float* b1    = (const float*)d_in[10];
    const float* W2    = (const float*)d_in[11];
    const float* b2    = (const float*)d_in[12];
    const float* Wm0   = (const float*)d_in[13];
    const float* bm0   = (const float*)d_in[14];
    const float* Wm1   = (const float*)d_in[15];
    const float* bm1   = (const float*)d_in[16];

    const int B = in_sizes[0];
    float* out  = (float*)d_out;
    float* xout = out;                  // [B]
    float* aout = out + B;              // [B, MOVE_N]

    float *wwT_ptr, *wbT_ptr, *base_ptr, *hidden_ptr;
    float *wm0r_ptr, *wm1r_ptr, *w0r_ptr, *w1r_ptr, *w2r_ptr;
    int* cnt_ptr;
    cudaGetSymbolAddress((void**)&wwT_ptr,    g_WwT);
    cudaGetSymbolAddress((void**)&wbT_ptr,    g_WbT);
    cudaGetSymbolAddress((void**)&base_ptr,   g_base);
    cudaGetSymbolAddress((void**)&hidden_ptr, g_hidden);
    cudaGetSymbolAddress((void**)&wm0r_ptr,   g_Wm0r);
    cudaGetSymbolAddress((void**)&wm1r_ptr,   g_Wm1r);
    cudaGetSymbolAddress((void**)&w0r_ptr,    g_W0r);
    cudaGetSymbolAddress((void**)&w1r_ptr,    g_W1r);
    cudaGetSymbolAddress((void**)&w2r_ptr,    g_W2r);
    cudaGetSymbolAddress((void**)&cnt_ptr,    g_cnt);

    static bool attr_done = false;
    if (!attr_done) {
        cudaFuncSetAttribute(gemm_mma<true>,
            cudaFuncAttributeMaxDynamicSharedMemorySize, 73728);
        cudaFuncSetAttribute(gemm_mma<false>,
            cudaFuncAttributeMaxDynamicSharedMemorySize, 73728);
        attr_done = true;
    }

    // zero per-position counters
    cudaMemsetAsync(cnt_ptr, 0, 2 * BATCH_MAX * sizeof(int));

    // streaming index extraction (long pole; launch first)
    {
        const int nchunks = B * HALF_KP4 / 256;
        scan_kernel<<<1184, 256>>>((const uint4*)white, (const uint4*)black,
                                   nchunks);
    }

    // table transposes (tf32-rounded)
    {
        dim3 grid(HALF_KP / 32, 256 / 32, 2);
        dim3 blk(32, 8);
        transpose_kernel<<<grid, blk>>>(Ww, wwT_ptr, Wb, wbT_ptr);
    }

    // all weight rounding in one launch
    round_all_kernel<<<1168, 256>>>(Wm0, wm0r_ptr, Wm1, wm1r_ptr,
                                    W0, w0r_ptr, W1, w1r_ptr, W2, w2r_ptr);

    // gather + pov select + value head (one block per position)
    gather_kernel<<<B, 256>>>(pov, wwT_ptr, bw, wbT_ptr, bb,
                              w0r_ptr, b0, w1r_ptr, b1, w2r_ptr, b2, xout);

    // hidden = tf32r(relu(base @ Wm0^T + bm0))   M=B, N=256, K=512
    {
        dim3 grid(256 / 128, B / 128);
        gemm_mma<true><<<grid, 256, 73728>>>(base_ptr, wm0r_ptr, bm0,
                                             hidden_ptr, B, 256, 512);
    }
    // a = relu(hidden @ Wm1^T + bm1)             M=B, N=4096, K=256
    {
        dim3 grid(MOVE_N / 128, B / 128);
        gemm_mma<false><<<grid, 256, 73728>>>(hidden_ptr, wm1r_ptr, bm1,
                                              aout, B, MOVE_N, 256);
    }
}

// round 12
// speedup vs baseline: 1.2887x; 1.2887x over previous
#include <cuda_runtime.h>
#include <cstdint>

// ---------------------------------------------------------------------------
// NNUE forward, TF32-faithful, target sm_100 (mma.sync tensor path).
//   memset:    zero per-position feature counters
//   scan:      OR-accumulate register-resident scan of white/black multihot
//   transpose: Ww/Wb (256 x 40960) -> (40960 x 256), tf32-rounded
//   round_all: Wm0/Wm1 -> tf32 scratch; round_heads: W0/W1 tf32 + transpose
//   gather:    ONE WARP PER POSITION: register gather-sum, no block syncs;
//              warp-private value head (fc0 coalesced via W0t, fc1/fc2 shfl)
//   gemm_mma:  mma.sync m16n8k8 tf32, 128x128 CTA tile, cp.async 2-stage
// ---------------------------------------------------------------------------

#define HALF_KP 40960
#define HALF_KP4 (HALF_KP / 4)
#define MOVE_N  4096
#define BATCH_MAX 4096

__device__ float g_WwT[(size_t)HALF_KP * 256];
__device__ float g_WbT[(size_t)HALF_KP * 256];
__device__ float g_base[BATCH_MAX * 512];
__device__ float g_hidden[BATCH_MAX * 256];
__device__ float g_Wm0r[256 * 512];
__device__ float g_Wm1r[(size_t)MOVE_N * 256];
__device__ float g_W0t[512 * 32];     // transposed: [k][o]
__device__ float g_W1t[32 * 32];      // transposed: [k][o]
__device__ float g_W2r[32];
__device__ int   g_cnt[2 * BATCH_MAX];
__device__ int   g_idx[2 * BATCH_MAX * 64];

__device__ __forceinline__ float tf32r(float x) {
    uint32_t u;
    asm("cvt.rna.tf32.f32 %0, %1;" : "=r"(u) : "f"(x));
    return __uint_as_float(u);
}

__device__ __forceinline__ uint32_t smem_to_u32(const void* p) {
    uint32_t a;
    asm("{ .reg .u64 t; cvta.to.shared.u64 t, %1; cvt.u32.u64 %0, t; }"
        : "=r"(a) : "l"(p));
    return a;
}

__device__ __forceinline__ void cp16(uint32_t dst, const void* src) {
    asm volatile("cp.async.cg.shared.global [%0], [%1], 16;"
                 :: "r"(dst), "l"(src) : "memory");
}

// ---------------------------------------------------------------------------
// Move-head weight rounding (float4 streams).
// ---------------------------------------------------------------------------
__global__ __launch_bounds__(256) void round_all_kernel(
    const float* __restrict__ Wm0, float* __restrict__ Wm0r,
    const float* __restrict__ Wm1, float* __restrict__ Wm1r)
{
    constexpr int nA = 256 * 512 / 4;
    constexpr int nB = MOVE_N * 256 / 4;
    constexpr int total = nA + nB;

    for (int i = blockIdx.x * 256 + threadIdx.x; i < total;
         i += gridDim.x * 256) {
        const float4* src;
        float4* dst;
        int j = i;
        if (j < nA) { src = (const float4*)Wm0; dst = (float4*)Wm0r; }
        else { j -= nA; src = (const float4*)Wm1; dst = (float4*)Wm1r; }
        float4 v = src[j];
        float4 w;
        w.x = tf32r(v.x); w.y = tf32r(v.y); w.z = tf32r(v.z); w.w = tf32r(v.w);
        dst[j] = w;
    }
}

// Value-head weights: tf32-round + transpose W0 -> [512][32], W1 -> [32][32].
__global__ __launch_bounds__(256) void round_heads_kernel(
    const float* __restrict__ W0, float* __restrict__ W0t,
    const float* __restrict__ W1, float* __restrict__ W1t,
    const float* __restrict__ W2, float* __restrict__ W2r)
{
    int i = blockIdx.x * 256 + threadIdx.x;
    if (i < 16384) {
        int o = i >> 9, k = i & 511;
        W0t[k * 32 + o] = tf32r(W0[i]);
    } else if (i < 17408) {
        int j = i - 16384;
        int o = j >> 5, k = j & 31;
        W1t[k * 32 + o] = tf32r(W1[j]);
    } else if (i < 17440) {
        W2r[i - 17408] = tf32r(W2[i - 17408]);
    }
}

// ---------------------------------------------------------------------------
// Fused transpose of both tables: [256, HALF_KP] -> [HALF_KP, 256], tf32.
// ---------------------------------------------------------------------------
__global__ __launch_bounds__(256) void transpose_kernel(
    const float* __restrict__ srcW, float* __restrict__ dstW,
    const float* __restrict__ srcB, float* __restrict__ dstB)
{
    __shared__ float tile[32][33];
    const float* src = blockIdx.z ? srcB : srcW;
    float*       dst = blockIdx.z ? dstB : dstW;
    const int f0 = blockIdx.x * 32;
    const int o0 = blockIdx.y * 32;
    const int tx = threadIdx.x;
    const int ty = threadIdx.y;
    #pragma unroll
    for (int i = 0; i < 32; i += 8)
        tile[ty + i][tx] = tf32r(src[(size_t)(o0 + ty + i) * HALF_KP + f0 + tx]);
    __syncthreads();
    #pragma unroll
    for (int i = 0; i < 32; i += 8)
        dst[(size_t)(f0 + ty + i) * 256 + o0 + tx] = tile[tx][ty + i];
}

// ---------------------------------------------------------------------------
// Scan: warp-cooperative 4KB chunks, register-resident OR-accumulate test.
// ---------------------------------------------------------------------------
__device__ __forceinline__ void scan_chunk(
    const uint4* __restrict__ arr, int base, int lane, int side)
{
    uint4 v[8];
    #pragma unroll
    for (int k = 0; k < 8; k++)
        v[k] = __ldcs(arr + base + k * 32 + lane);
    uint32_t a0 = 0, a1 = 0;
    #pragma unroll
    for (int k = 0; k < 8; k++) {
        a0 |= v[k].x | v[k].y;
        a1 |= v[k].z | v[k].w;
    }
    if (a0 | a1) {
        const int pos   = base / HALF_KP4;
        const int fbase = (base - pos * HALF_KP4) * 4;
        int* cnt = &g_cnt[side + pos];
        int* idx = &g_idx[(size_t)(side + pos) * 64];
        #pragma unroll
        for (int k = 0; k < 8; k++) {
            if (v[k].x | v[k].y | v[k].z | v[k].w) {
                const int f0 = fbase + (k * 32 + lane) * 4;
                if (v[k].x) { int p = atomicAdd(cnt, 1); if (p < 64) idx[p] = f0;     }
                if (v[k].y) { int p = atomicAdd(cnt, 1); if (p < 64) idx[p] = f0 + 1; }
                if (v[k].z) { int p = atomicAdd(cnt, 1); if (p < 64) idx[p] = f0 + 2; }
                if (v[k].w) { int p = atomicAdd(cnt, 1); if (p < 64) idx[p] = f0 + 3; }
            }
        }
    }
}

__global__ __launch_bounds__(256) void scan_kernel(
    const uint4* __restrict__ white, const uint4* __restrict__ black,
    int nchunks)
{
    const int lane  = threadIdx.x & 31;
    const int warp0 = blockIdx.x * 8 + (threadIdx.x >> 5);
    const int nwarp = gridDim.x * 8;
    for (int c = warp0; c < nchunks; c += nwarp) {
        const int base = c * 256;
        scan_chunk(white, base, lane, 0);
        scan_chunk(black, base, lane, BATCH_MAX);
    }
}

// ---------------------------------------------------------------------------
// Gather + value head: ONE WARP PER POSITION. No block-level syncs.
// Lane l owns float4 columns l and l+32 of each 1KB row.
// ---------------------------------------------------------------------------
__global__ __launch_bounds__(256) void gather_kernel(
    const float* __restrict__ pov,
    const float* __restrict__ WwT, const float* __restrict__ bw,
    const float* __restrict__ WbT, const float* __restrict__ bb,
    const float* __restrict__ W0t, const float* __restrict__ b0,
    const float* __restrict__ W1t, const float* __restrict__ b1,
    const float* __restrict__ W2r, const float* __restrict__ b2,
    float* __restrict__ xout)
{
    const int w = threadIdx.x >> 5;
    const int l = threadIdx.x & 31;
    const int b = blockIdx.x * 8 + w;

    __shared__ __align__(16) int   sIdx[8][128];
    __shared__ __align__(16) float sbase[8][512];

    const int nW = min(g_cnt[b], 64);
    const int nB = min(g_cnt[BATCH_MAX + b], 64);

    // stage indices (4 per lane)
    sIdx[w][l]      = g_idx[b * 64 + l];
    sIdx[w][l + 32] = g_idx[b * 64 + l + 32];
    sIdx[w][l + 64] = g_idx[(size_t)(BATCH_MAX + b) * 64 + l];
    sIdx[w][l + 96] = g_idx[(size_t)(BATCH_MAX + b) * 64 + l + 32];
    __syncwarp();

    // --- white gather: 2-row unroll, 4 accumulators, 4 loads in flight ---
    float4 aw0 = {0.f,0.f,0.f,0.f}, aw1 = {0.f,0.f,0.f,0.f};
    float4 aw2 = {0.f,0.f,0.f,0.f}, aw3 = {0.f,0.f,0.f,0.f};
    {
        int i = 0;
        for (; i + 1 < nW; i += 2) {
            const float4* r0 = (const float4*)(WwT + (size_t)sIdx[w][i]     * 256);
            const float4* r1 = (const float4*)(WwT + (size_t)sIdx[w][i + 1] * 256);
            const float4 v0 = r0[l], v1 = r0[l + 32];
            const float4 v2 = r1[l], v3 = r1[l + 32];
            aw0.x += v0.x; aw0.y += v0.y; aw0.z += v0.z; aw0.w += v0.w;
            aw1.x += v1.x; aw1.y += v1.y; aw1.z += v1.z; aw1.w += v1.w;
            aw2.x += v2.x; aw2.y += v2.y; aw2.z += v2.z; aw2.w += v2.w;
            aw3.x += v3.x; aw3.y += v3.y; aw3.z += v3.z; aw3.w += v3.w;
        }
        if (i < nW) {
            const float4* r0 = (const float4*)(WwT + (size_t)sIdx[w][i] * 256);
            const float4 v0 = r0[l], v1 = r0[l + 32];
            aw0.x += v0.x; aw0.y += v0.y; aw0.z += v0.z; aw0.w += v0.w;
            aw1.x += v1.x; aw1.y += v1.y; aw1.z += v1.z; aw1.w += v1.w;
        }
        aw0.x += aw2.x; aw0.y += aw2.y; aw0.z += aw2.z; aw0.w += aw2.w;
        aw1.x += aw3.x; aw1.y += aw3.y; aw1.z += aw3.z; aw1.w += aw3.w;
    }
    // --- black gather ---
    float4 ab0 = {0.f,0.f,0.f,0.f}, ab1 = {0.f,0.f,0.f,0.f};
    float4 ab2 = {0.f,0.f,0.f,0.f}, ab3 = {0.f,0.f,0.f,0.f};
    {
        int i = 0;
        for (; i + 1 < nB; i += 2) {
            const float4* r0 = (const float4*)(WbT + (size_t)sIdx[w][64 + i]     * 256);
            const float4* r1 = (const float4*)(WbT + (size_t)sIdx[w][64 + i + 1] * 256);
            const float4 v0 = r0[l], v1 = r0[l + 32];
            const float4 v2 = r1[l], v3 = r1[l + 32];
            ab0.x += v0.x; ab0.y += v0.y; ab0.z += v0.z; ab0.w += v0.w;
            ab1.x += v1.x; ab1.y += v1.y; ab1.z += v1.z; ab1.w += v1.w;
            ab2.x += v2.x; ab2.y += v2.y; ab2.z += v2.z; ab2.w += v2.w;
            ab3.x += v3.x; ab3.y += v3.y; ab3.z += v3.z; ab3.w += v3.w;
        }
        if (i < nB) {
            const float4* r0 = (const float4*)(WbT + (size_t)sIdx[w][64 + i] * 256);
            const float4 v0 = r0[l], v1 = r0[l + 32];
            ab0.x += v0.x; ab0.y += v0.y; ab0.z += v0.z; ab0.w += v0.w;
            ab1.x += v1.x; ab1.y += v1.y; ab1.z += v1.z; ab1.w += v1.w;
        }
        ab0.x += ab2.x; ab0.y += ab2.y; ab0.z += ab2.z; ab0.w += ab2.w;
        ab1.x += ab3.x; ab1.y += ab3.y; ab1.z += ab3.z; ab1.w += ab3.w;
    }

    // biases
    const float4 bw0 = *(const float4*)(bw + 4 * l);
    const float4 bw1 = *(const float4*)(bw + 128 + 4 * l);
    const float4 bb0 = *(const float4*)(bb + 4 * l);
    const float4 bb1 = *(const float4*)(bb + 128 + 4 * l);
    aw0.x += bw0.x; aw0.y += bw0.y; aw0.z += bw0.z; aw0.w += bw0.w;
    aw1.x += bw1.x; aw1.y += bw1.y; aw1.z += bw1.z; aw1.w += bw1.w;
    ab0.x += bb0.x; ab0.y += bb0.y; ab0.z += bb0.z; ab0.w += bb0.w;
    ab1.x += bb1.x; ab1.y += bb1.y; ab1.z += bb1.z; ab1.w += bb1.w;

    // pov select + relu + tf32 round
    const bool p = (pov[b] != 0.f);
    const float4 f0v = p ? aw0 : ab0;     // base cols   4l..
    const float4 f1v = p ? aw1 : ab1;     // base cols 128+4l..
    const float4 s0v = p ? ab0 : aw0;     // base cols 256+4l..
    const float4 s1v = p ? ab1 : aw1;     // base cols 384+4l..

    float4 o0, o1, o2, o3;
    o0.x = tf32r(fmaxf(f0v.x, 0.f)); o0.y = tf32r(fmaxf(f0v.y, 0.f));
    o0.z = tf32r(fmaxf(f0v.z, 0.f)); o0.w = tf32r(fmaxf(f0v.w, 0.f));
    o1.x = tf32r(fmaxf(f1v.x, 0.f)); o1.y = tf32r(fmaxf(f1v.y, 0.f));
    o1.z = tf32r(fmaxf(f1v.z, 0.f)); o1.w = tf32r(fmaxf(f1v.w, 0.f));
    o2.x = tf32r(fmaxf(s0v.x, 0.f)); o2.y = tf32r(fmaxf(s0v.y, 0.f));
    o2.z = tf32r(fmaxf(s0v.z, 0.f)); o2.w = tf32r(fmaxf(s0v.w, 0.f));
    o3.x = tf32r(fmaxf(s1v.x, 0.f)); o3.y = tf32r(fmaxf(s1v.y, 0.f));
    o3.z = tf32r(fmaxf(s1v.z, 0.f)); o3.w = tf32r(fmaxf(s1v.w, 0.f));

    float* baserow = g_base + (size_t)b * 512;
    *(float4*)(baserow + 4 * l)        = o0;
    *(float4*)(baserow + 128 + 4 * l)  = o1;
    *(float4*)(baserow + 256 + 4 * l)  = o2;
    *(float4*)(baserow + 384 + 4 * l)  = o3;
    *(float4*)(&sbase[w][4 * l])       = o0;
    *(float4*)(&sbase[w][128 + 4 * l]) = o1;
    *(float4*)(&sbase[w][256 + 4 * l]) = o2;
    *(float4*)(&sbase[w][384 + 4 * l]) = o3;
    __syncwarp();

    // fc0: lane l computes output l. W0t coalesced; sbase broadcast LDS.
    float h0;
    {
        float s0 = 0.f, s1 = 0.f, s2 = 0.f, s3 = 0.f;
        const float* base_s = sbase[w];
        #pragma unroll 4
        for (int k = 0; k < 512; k += 4) {
            s0 += W0t[(k + 0) * 32 + l] * base_s[k + 0];
            s1 += W0t[(k + 1) * 32 + l] * base_s[k + 1];
            s2 += W0t[(k + 2) * 32 + l] * base_s[k + 2];
            s3 += W0t[(k + 3) * 32 + l] * base_s[k + 3];
        }
        h0 = tf32r(fmaxf(((s0 + s1) + (s2 + s3)) + b0[l], 0.f));
    }
    // fc1 via shfl broadcast
    float h1;
    {
        float s = 0.f;
        #pragma unroll
        for (int k = 0; k < 32; k++) {
            const float h0k = __shfl_sync(0xffffffffu, h0, k);
            s += W1t[k * 32 + l] * h0k;
        }
        h1 = tf32r(fmaxf(s + b1[l], 0.f));
    }
    // fc2: per-lane product + shfl reduce
    {
        float s = W2r[l] * h1;
        s += __shfl_down_sync(0xffffffffu, s, 16);
        s += __shfl_down_sync(0xffffffffu, s, 8);
        s += __shfl_down_sync(0xffffffffu, s, 4);
        s += __shfl_down_sync(0xffffffffu, s, 2);
        s += __shfl_down_sync(0xffffffffu, s, 1);
        if (l == 0) xout[b] = s + b2[0];
    }
}

// ---------------------------------------------------------------------------
// TF32 mma.sync NT GEMM: C[M,N] = relu(A[M,K] @ Bm[N,K]^T + bias[N])
// 128x128 CTA tile, 8 warps, warp 64x32. K-chunk 32, 2-stage cp.async.
// ---------------------------------------------------------------------------
template <bool ROUND_OUT>
__global__ __launch_bounds__(256) void gemm_mma(
    const float* __restrict__ A,
    const float* __restrict__ Bm,
    const float* __restrict__ bias,
    float* __restrict__ C,
    int M, int N, int K)
{
    extern __shared__ float smem[];
    constexpr int TILE = 4608;
    constexpr int STAGE = 2 * TILE;

    const int tid  = threadIdx.x;
    const int wid  = tid >> 5;
    const int lane = tid & 31;
    const int q    = lane >> 2;
    const int r    = lane & 3;
    const int wm   = (wid & 1) * 64;
    const int wn   = (wid >> 1) * 32;
    const int m0   = blockIdx.y * 128;
    const int n0   = blockIdx.x * 128;

    const uint32_t sb = smem_to_u32(smem);

    float acc[4][4][4];
    #pragma unroll
    for (int i = 0; i < 4; i++)
        #pragma unroll
        for (int j = 0; j < 4; j++)
            #pragma unroll
            for (int c = 0; c < 4; c++) acc[i][j][c] = 0.f;

    const int nK = K / 32;

    auto load_chunk = [&](int kc, int stage) {
        const uint32_t aAddr = sb + stage * STAGE * 4;
        const uint32_t bAddr = aAddr + TILE * 4;
        const int k0 = kc * 32;
        #pragma unroll
        for (int i = 0; i < 4; i++) {
            int u  = i * 256 + tid;
            int rr = u >> 3;
            int c4 = u & 7;
            uint32_t off = (uint32_t)(rr * 36 + c4 * 4) * 4;
            cp16(aAddr + off, A  + (size_t)(m0 + rr) * K + k0 + c4 * 4);
            cp16(bAddr + off, Bm + (size_t)(n0 + rr) * K + k0 + c4 * 4);
        }
        asm volatile("cp.async.commit_group;" ::: "memory");
    };

    load_chunk(0, 0);

    for (int kc = 0; kc < nK; kc++) {
        const int stage = kc & 1;
        if (kc + 1 < nK) {
            load_chunk(kc + 1, stage ^ 1);
            asm volatile("cp.async.wait_group 1;" ::: "memory");
        } else {
            asm volatile("cp.async.wait_group 0;" ::: "memory");
        }
        __syncthreads();

        const float* Ab = smem + stage * STAGE;
        const float* Bb = Ab + TILE;

        #pragma unroll
        for (int ks = 0; ks < 4; ks++) {
            const int k = ks * 8;
            uint32_t a[4][4];
            #pragma unroll
            for (int i = 0; i < 4; i++) {
                const int m = wm + 16 * i + q;
                a[i][0] = __float_as_uint(Ab[m * 36 + k + r]);
                a[i][1] = __float_as_uint(Ab[(m + 8) * 36 + k + r]);
                a[i][2] = __float_as_uint(Ab[m * 36 + k + r + 4]);
                a[i][3] = __float_as_uint(Ab[(m + 8) * 36 + k + r + 4]);
            }
            uint32_t bfr[4][2];
            #pragma unroll
            for (int j = 0; j < 4; j++) {
                const int n = wn + 8 * j + q;
                bfr[j][0] = __float_as_uint(Bb[n * 36 + k + r]);
                bfr[j][1] = __float_as_uint(Bb[n * 36 + k + r + 4]);
            }
            #pragma unroll
            for (int i = 0; i < 4; i++)
                #pragma unroll
                for (int j = 0; j < 4; j++) {
                    asm volatile(
                        "mma.sync.aligned.m16n8k8.row.col.f32.tf32.tf32.f32 "
                        "{%0,%1,%2,%3}, {%4,%5,%6,%7}, {%8,%9}, {%0,%1,%2,%3};"
                        : "+f"(acc[i][j][0]), "+f"(acc[i][j][1]),
                          "+f"(acc[i][j][2]), "+f"(acc[i][j][3])
                        : "r"(a[i][0]), "r"(a[i][1]), "r"(a[i][2]), "r"(a[i][3]),
                          "r"(bfr[j][0]), "r"(bfr[j][1]));
                }
        }
        __syncthreads();
    }

    #pragma unroll
    for (int i = 0; i < 4; i++) {
        #pragma unroll
        for (int j = 0; j < 4; j++) {
            const int row = m0 + wm + 16 * i + q;
            const int col = n0 + wn + 8 * j + 2 * r;
            const float bj0 = bias[col];
            const float bj1 = bias[col + 1];
            float v00 = fmaxf(acc[i][j][0] + bj0, 0.f);
            float v01 = fmaxf(acc[i][j][1] + bj1, 0.f);
            float v10 = fmaxf(acc[i][j][2] + bj0, 0.f);
            float v11 = fmaxf(acc[i][j][3] + bj1, 0.f);
            if (ROUND_OUT) {
                v00 = tf32r(v00); v01 = tf32r(v01);
                v10 = tf32r(v10); v11 = tf32r(v11);
            }
            float2 lo = make_float2(v00, v01);
            float2 hi = make_float2(v10, v11);
            *(float2*)(C + (size_t)row * N + col)       = lo;
            *(float2*)(C + (size_t)(row + 8) * N + col) = hi;
        }
    }
}

// ---------------------------------------------------------------------------
extern "C" void kernel_launch(void* const* d_in, const int* in_sizes, int n_in,
                              void* d_out, int out_size)
{
    const float* pov   = (const float*)d_in[0];
    const float* white = (const float*)d_in[1];
    const float* black = (const float*)d_in[2];
    const float* Ww    = (const float*)d_in[3];
    const float* bw    = (const float*)d_in[4];
    const float* Wb    = (const float*)d_in[5];
    const float* bb    = (const float*)d_in[6];
    const float* W0    = (const float*)d_in[7];
    const float* b0    = (const float*)d_in[8];
    const float* W1    = (const float*)d_in[9];
    const float* b1    = (const float*)d_in[10];
    const float* W2    = (const float*)d_in[11];
    const float* b2    = (const float*)d_in[12];
    const float* Wm0   = (const float*)d_in[13];
    const float* bm0   = (const float*)d_in[14];
    const float* Wm1   = (const float*)d_in[15];
    const float* bm1   = (const float*)d_in[16];

    const int B = in_sizes[0];
    float* out  = (float*)d_out;
    float* xout = out;                  // [B]
    float* aout = out + B;              // [B, MOVE_N]

    float *wwT_ptr, *wbT_ptr, *base_ptr, *hidden_ptr;
    float *wm0r_ptr, *wm1r_ptr, *w0t_ptr, *w1t_ptr, *w2r_ptr;
    int* cnt_ptr;
    cudaGetSymbolAddress((void**)&wwT_ptr,    g_WwT);
    cudaGetSymbolAddress((void**)&wbT_ptr,    g_WbT);
    cudaGetSymbolAddress((void**)&base_ptr,   g_base);
    cudaGetSymbolAddress((void**)&hidden_ptr, g_hidden);
    cudaGetSymbolAddress((void**)&wm0r_ptr,   g_Wm0r);
    cudaGetSymbolAddress((void**)&wm1r_ptr,   g_Wm1r);
    cudaGetSymbolAddress((void**)&w0t_ptr,    g_W0t);
    cudaGetSymbolAddress((void**)&w1t_ptr,    g_W1t);
    cudaGetSymbolAddress((void**)&w2r_ptr,    g_W2r);
    cudaGetSymbolAddress((void**)&cnt_ptr,    g_cnt);

    static bool attr_done = false;
    if (!attr_done) {
        cudaFuncSetAttribute(gemm_mma<true>,
            cudaFuncAttributeMaxDynamicSharedMemorySize, 73728);
        cudaFuncSetAttribute(gemm_mma<false>,
            cudaFuncAttributeMaxDynamicSharedMemorySize, 73728);
        attr_done = true;
    }

    // zero per-position counters
    cudaMemsetAsync(cnt_ptr, 0, 2 * BATCH_MAX * sizeof(int));

    // streaming index extraction (long pole; launch first)
    {
        const int nchunks = B * HALF_KP4 / 256;
        scan_kernel<<<1184, 256>>>((const uint4*)white, (const uint4*)black,
                                   nchunks);
    }

    // table transposes (tf32-rounded)
    {
        dim3 grid(HALF_KP / 32, 256 / 32, 2);
        dim3 blk(32, 8);
        transpose_kernel<<<grid, blk>>>(Ww, wwT_ptr, Wb, wbT_ptr);
    }

    // weight prep
    round_all_kernel<<<1152, 256>>>(Wm0, wm0r_ptr, Wm1, wm1r_ptr);
    round_heads_kernel<<<69, 256>>>(W0, w0t_ptr, W1, w1t_ptr, W2, w2r_ptr);

    // gather + value head: one warp per position
    gather_kernel<<<B / 8, 256>>>(pov, wwT_ptr, bw, wbT_ptr, bb,
                                  w0t_ptr, b0, w1t_ptr, b1, w2r_ptr, b2, xout);

    // hidden = tf32r(relu(base @ Wm0^T + bm0))   M=B, N=256, K=512
    {
        dim3 grid(256 / 128, B / 128);
        gemm_mma<true><<<grid, 256, 73728>>>(base_ptr, wm0r_ptr, bm0,
                                             hidden_ptr, B, 256, 512);
    }
    // a = relu(hidden @ Wm1^T + bm1)             M=B, N=4096, K=256
    {
        dim3 grid(MOVE_N / 128, B / 128);
        gemm_mma<false><<<grid, 256, 73728>>>(hidden_ptr, wm1r_ptr, bm1,
                                              aout, B, MOVE_N, 256);
    }
}

// round 13
// speedup vs baseline: 1.3057x; 1.0131x over previous
#include <cuda_runtime.h>
#include <cstdint>

// ---------------------------------------------------------------------------
// NNUE forward, TF32-faithful, target sm_100 (mma.sync tensor path).
//   main stream:  memset -> scan ----------------\
//   side stream:  transpose, round_all/heads -----+--> gather -> gemmB -> gemmC
//   (fork/join via events; capture-compatible)
//   gather:    ONE WARP PER POSITION, register gather-sum + warp value head
//   gemm_mma:  mma.sync m16n8k8 tf32, 128x128 CTA tile, cp.async 2-stage
// ---------------------------------------------------------------------------

#define HALF_KP 40960
#define HALF_KP4 (HALF_KP / 4)
#define MOVE_N  4096
#define BATCH_MAX 4096

__device__ float g_WwT[(size_t)HALF_KP * 256];
__device__ float g_WbT[(size_t)HALF_KP * 256];
__device__ float g_base[BATCH_MAX * 512];
__device__ float g_hidden[BATCH_MAX * 256];
__device__ float g_Wm0r[256 * 512];
__device__ float g_Wm1r[(size_t)MOVE_N * 256];
__device__ float g_W0t[512 * 32];     // transposed: [k][o]
__device__ float g_W1t[32 * 32];      // transposed: [k][o]
__device__ float g_W2r[32];
__device__ int   g_cnt[2 * BATCH_MAX];
__device__ int   g_idx[2 * BATCH_MAX * 64];

__device__ __forceinline__ float tf32r(float x) {
    uint32_t u;
    asm("cvt.rna.tf32.f32 %0, %1;" : "=r"(u) : "f"(x));
    return __uint_as_float(u);
}

__device__ __forceinline__ uint32_t smem_to_u32(const void* p) {
    uint32_t a;
    asm("{ .reg .u64 t; cvta.to.shared.u64 t, %1; cvt.u32.u64 %0, t; }"
        : "=r"(a) : "l"(p));
    return a;
}

__device__ __forceinline__ void cp16(uint32_t dst, const void* src) {
    asm volatile("cp.async.cg.shared.global [%0], [%1], 16;"
                 :: "r"(dst), "l"(src) : "memory");
}

// ---------------------------------------------------------------------------
// Move-head weight rounding (float4 streams).
// ---------------------------------------------------------------------------
__global__ __launch_bounds__(256) void round_all_kernel(
    const float* __restrict__ Wm0, float* __restrict__ Wm0r,
    const float* __restrict__ Wm1, float* __restrict__ Wm1r)
{
    constexpr int nA = 256 * 512 / 4;
    constexpr int nB = MOVE_N * 256 / 4;
    constexpr int total = nA + nB;

    for (int i = blockIdx.x * 256 + threadIdx.x; i < total;
         i += gridDim.x * 256) {
        const float4* src;
        float4* dst;
        int j = i;
        if (j < nA) { src = (const float4*)Wm0; dst = (float4*)Wm0r; }
        else { j -= nA; src = (const float4*)Wm1; dst = (float4*)Wm1r; }
        float4 v = src[j];
        float4 w;
        w.x = tf32r(v.x); w.y = tf32r(v.y); w.z = tf32r(v.z); w.w = tf32r(v.w);
        dst[j] = w;
    }
}

// Value-head weights: tf32-round + transpose W0 -> [512][32], W1 -> [32][32].
__global__ __launch_bounds__(256) void round_heads_kernel(
    const float* __restrict__ W0, float* __restrict__ W0t,
    const float* __restrict__ W1, float* __restrict__ W1t,
    const float* __restrict__ W2, float* __restrict__ W2r)
{
    int i = blockIdx.x * 256 + threadIdx.x;
    if (i < 16384) {
        int o = i >> 9, k = i & 511;
        W0t[k * 32 + o] = tf32r(W0[i]);
    } else if (i < 17408) {
        int j = i - 16384;
        int o = j >> 5, k = j & 31;
        W1t[k * 32 + o] = tf32r(W1[j]);
    } else if (i < 17440) {
        W2r[i - 17408] = tf32r(W2[i - 17408]);
    }
}

// ---------------------------------------------------------------------------
// Fused transpose of both tables: [256, HALF_KP] -> [HALF_KP, 256], tf32.
// ---------------------------------------------------------------------------
__global__ __launch_bounds__(256) void transpose_kernel(
    const float* __restrict__ srcW, float* __restrict__ dstW,
    const float* __restrict__ srcB, float* __restrict__ dstB)
{
    __shared__ float tile[32][33];
    const float* src = blockIdx.z ? srcB : srcW;
    float*       dst = blockIdx.z ? dstB : dstW;
    const int f0 = blockIdx.x * 32;
    const int o0 = blockIdx.y * 32;
    const int tx = threadIdx.x;
    const int ty = threadIdx.y;
    #pragma unroll
    for (int i = 0; i < 32; i += 8)
        tile[ty + i][tx] = tf32r(src[(size_t)(o0 + ty + i) * HALF_KP + f0 + tx]);
    __syncthreads();
    #pragma unroll
    for (int i = 0; i < 32; i += 8)
        dst[(size_t)(f0 + ty + i) * 256 + o0 + tx] = tile[tx][ty + i];
}

// ---------------------------------------------------------------------------
// Scan: warp-cooperative 4KB chunks, register-resident OR-accumulate test.
// ---------------------------------------------------------------------------
__device__ __forceinline__ void scan_chunk(
    const uint4* __restrict__ arr, int base, int lane, int side)
{
    uint4 v[8];
    #pragma unroll
    for (int k = 0; k < 8; k++)
        v[k] = __ldcs(arr + base + k * 32 + lane);
    uint32_t a0 = 0, a1 = 0;
    #pragma unroll
    for (int k = 0; k < 8; k++) {
        a0 |= v[k].x | v[k].y;
        a1 |= v[k].z | v[k].w;
    }
    if (a0 | a1) {
        const int pos   = base / HALF_KP4;
        const int fbase = (base - pos * HALF_KP4) * 4;
        int* cnt = &g_cnt[side + pos];
        int* idx = &g_idx[(size_t)(side + pos) * 64];
        #pragma unroll
        for (int k = 0; k < 8; k++) {
            if (v[k].x | v[k].y | v[k].z | v[k].w) {
                const int f0 = fbase + (k * 32 + lane) * 4;
                if (v[k].x) { int p = atomicAdd(cnt, 1); if (p < 64) idx[p] = f0;     }
                if (v[k].y) { int p = atomicAdd(cnt, 1); if (p < 64) idx[p] = f0 + 1; }
                if (v[k].z) { int p = atomicAdd(cnt, 1); if (p < 64) idx[p] = f0 + 2; }
                if (v[k].w) { int p = atomicAdd(cnt, 1); if (p < 64) idx[p] = f0 + 3; }
            }
        }
    }
}

__global__ __launch_bounds__(256) void scan_kernel(
    const uint4* __restrict__ white, const uint4* __restrict__ black,
    int nchunks)
{
    const int lane  = threadIdx.x & 31;
    const int warp0 = blockIdx.x * 8 + (threadIdx.x >> 5);
    const int nwarp = gridDim.x * 8;
    for (int c = warp0; c < nchunks; c += nwarp) {
        const int base = c * 256;
        scan_chunk(white, base, lane, 0);
        scan_chunk(black, base, lane, BATCH_MAX);
    }
}

// ---------------------------------------------------------------------------
// Gather + value head: ONE WARP PER POSITION. No block-level syncs.
// Lane l owns float4 columns l and l+32 of each 1KB row.
// ---------------------------------------------------------------------------
__global__ __launch_bounds__(256) void gather_kernel(
    const float* __restrict__ pov,
    const float* __restrict__ WwT, const float* __restrict__ bw,
    const float* __restrict__ WbT, const float* __restrict__ bb,
    const float* __restrict__ W0t, const float* __restrict__ b0,
    const float* __restrict__ W1t, const float* __restrict__ b1,
    const float* __restrict__ W2r, const float* __restrict__ b2,
    float* __restrict__ xout)
{
    const int w = threadIdx.x >> 5;
    const int l = threadIdx.x & 31;
    const int b = blockIdx.x * 8 + w;

    __shared__ __align__(16) int   sIdx[8][128];
    __shared__ __align__(16) float sbase[8][512];

    const int nW = min(g_cnt[b], 64);
    const int nB = min(g_cnt[BATCH_MAX + b], 64);

    sIdx[w][l]      = g_idx[b * 64 + l];
    sIdx[w][l + 32] = g_idx[b * 64 + l + 32];
    sIdx[w][l + 64] = g_idx[(size_t)(BATCH_MAX + b) * 64 + l];
    sIdx[w][l + 96] = g_idx[(size_t)(BATCH_MAX + b) * 64 + l + 32];
    __syncwarp();

    float4 aw0 = {0.f,0.f,0.f,0.f}, aw1 = {0.f,0.f,0.f,0.f};
    float4 aw2 = {0.f,0.f,0.f,0.f}, aw3 = {0.f,0.f,0.f,0.f};
    {
        int i = 0;
        for (; i + 1 < nW; i += 2) {
            const float4* r0 = (const float4*)(WwT + (size_t)sIdx[w][i]     * 256);
            const float4* r1 = (const float4*)(WwT + (size_t)sIdx[w][i + 1] * 256);
            const float4 v0 = r0[l], v1 = r0[l + 32];
            const float4 v2 = r1[l], v3 = r1[l + 32];
            aw0.x += v0.x; aw0.y += v0.y; aw0.z += v0.z; aw0.w += v0.w;
            aw1.x += v1.x; aw1.y += v1.y; aw1.z += v1.z; aw1.w += v1.w;
            aw2.x += v2.x; aw2.y += v2.y; aw2.z += v2.z; aw2.w += v2.w;
            aw3.x += v3.x; aw3.y += v3.y; aw3.z += v3.z; aw3.w += v3.w;
        }
        if (i < nW) {
            const float4* r0 = (const float4*)(WwT + (size_t)sIdx[w][i] * 256);
            const float4 v0 = r0[l], v1 = r0[l + 32];
            aw0.x += v0.x; aw0.y += v0.y; aw0.z += v0.z; aw0.w += v0.w;
            aw1.x += v1.x; aw1.y += v1.y; aw1.z += v1.z; aw1.w += v1.w;
        }
        aw0.x += aw2.x; aw0.y += aw2.y; aw0.z += aw2.z; aw0.w += aw2.w;
        aw1.x += aw3.x; aw1.y += aw3.y; aw1.z += aw3.z; aw1.w += aw3.w;
    }
    float4 ab0 = {0.f,0.f,0.f,0.f}, ab1 = {0.f,0.f,0.f,0.f};
    float4 ab2 = {0.f,0.f,0.f,0.f}, ab3 = {0.f,0.f,0.f,0.f};
    {
        int i = 0;
        for (; i + 1 < nB; i += 2) {
            const float4* r0 = (const float4*)(WbT + (size_t)sIdx[w][64 + i]     * 256);
            const float4* r1 = (const float4*)(WbT + (size_t)sIdx[w][64 + i + 1] * 256);
            const float4 v0 = r0[l], v1 = r0[l + 32];
            const float4 v2 = r1[l], v3 = r1[l + 32];
            ab0.x += v0.x; ab0.y += v0.y; ab0.z += v0.z; ab0.w += v0.w;
            ab1.x += v1.x; ab1.y += v1.y; ab1.z += v1.z; ab1.w += v1.w;
            ab2.x += v2.x; ab2.y += v2.y; ab2.z += v2.z; ab2.w += v2.w;
            ab3.x += v3.x; ab3.y += v3.y; ab3.z += v3.z; ab3.w += v3.w;
        }
        if (i < nB) {
            const float4* r0 = (const float4*)(WbT + (size_t)sIdx[w][64 + i] * 256);
            const float4 v0 = r0[l], v1 = r0[l + 32];
            ab0.x += v0.x; ab0.y += v0.y; ab0.z += v0.z; ab0.w += v0.w;
            ab1.x += v1.x; ab1.y += v1.y; ab1.z += v1.z; ab1.w += v1.w;
        }
        ab0.x += ab2.x; ab0.y += ab2.y; ab0.z += ab2.z; ab0.w += ab2.w;
        ab1.x += ab3.x; ab1.y += ab3.y; ab1.z += ab3.z; ab1.w += ab3.w;
    }

    const float4 bw0 = *(const float4*)(bw + 4 * l);
    const float4 bw1 = *(const float4*)(bw + 128 + 4 * l);
    const float4 bb0 = *(const float4*)(bb + 4 * l);
    const float4 bb1 = *(const float4*)(bb + 128 + 4 * l);
    aw0.x += bw0.x; aw0.y += bw0.y; aw0.z += bw0.z; aw0.w += bw0.w;
    aw1.x += bw1.x; aw1.y += bw1.y; aw1.z += bw1.z; aw1.w += bw1.w;
    ab0.x += bb0.x; ab0.y += bb0.y; ab0.z += bb0.z; ab0.w += bb0.w;
    ab1.x += bb1.x; ab1.y += bb1.y; ab1.z += bb1.z; ab1.w += bb1.w;

    const bool p = (pov[b] != 0.f);
    const float4 f0v = p ? aw0 : ab0;
    const float4 f1v = p ? aw1 : ab1;
    const float4 s0v = p ? ab0 : aw0;
    const float4 s1v = p ? ab1 : aw1;

    float4 o0, o1, o2, o3;
    o0.x = tf32r(fmaxf(f0v.x, 0.f)); o0.y = tf32r(fmaxf(f0v.y, 0.f));
    o0.z = tf32r(fmaxf(f0v.z, 0.f)); o0.w = tf32r(fmaxf(f0v.w, 0.f));
    o1.x = tf32r(fmaxf(f1v.x, 0.f)); o1.y = tf32r(fmaxf(f1v.y, 0.f));
    o1.z = tf32r(fmaxf(f1v.z, 0.f)); o1.w = tf32r(fmaxf(f1v.w, 0.f));
    o2.x = tf32r(fmaxf(s0v.x, 0.f)); o2.y = tf32r(fmaxf(s0v.y, 0.f));
    o2.z = tf32r(fmaxf(s0v.z, 0.f)); o2.w = tf32r(fmaxf(s0v.w, 0.f));
    o3.x = tf32r(fmaxf(s1v.x, 0.f)); o3.y = tf32r(fmaxf(s1v.y, 0.f));
    o3.z = tf32r(fmaxf(s1v.z, 0.f)); o3.w = tf32r(fmaxf(s1v.w, 0.f));

    float* baserow = g_base + (size_t)b * 512;
    *(float4*)(baserow + 4 * l)        = o0;
    *(float4*)(baserow + 128 + 4 * l)  = o1;
    *(float4*)(baserow + 256 + 4 * l)  = o2;
    *(float4*)(baserow + 384 + 4 * l)  = o3;
    *(float4*)(&sbase[w][4 * l])       = o0;
    *(float4*)(&sbase[w][128 + 4 * l]) = o1;
    *(float4*)(&sbase[w][256 + 4 * l]) = o2;
    *(float4*)(&sbase[w][384 + 4 * l]) = o3;
    __syncwarp();

    float h0;
    {
        float s0 = 0.f, s1 = 0.f, s2 = 0.f, s3 = 0.f;
        const float* base_s = sbase[w];
        #pragma unroll 4
        for (int k = 0; k < 512; k += 4) {
            s0 += W0t[(k + 0) * 32 + l] * base_s[k + 0];
            s1 += W0t[(k + 1) * 32 + l] * base_s[k + 1];
            s2 += W0t[(k + 2) * 32 + l] * base_s[k + 2];
            s3 += W0t[(k + 3) * 32 + l] * base_s[k + 3];
        }
        h0 = tf32r(fmaxf(((s0 + s1) + (s2 + s3)) + b0[l], 0.f));
    }
    float h1;
    {
        float s = 0.f;
        #pragma unroll
        for (int k = 0; k < 32; k++) {
            const float h0k = __shfl_sync(0xffffffffu, h0, k);
            s += W1t[k * 32 + l] * h0k;
        }
        h1 = tf32r(fmaxf(s + b1[l], 0.f));
    }
    {
        float s = W2r[l] * h1;
        s += __shfl_down_sync(0xffffffffu, s, 16);
        s += __shfl_down_sync(0xffffffffu, s, 8);
        s += __shfl_down_sync(0xffffffffu, s, 4);
        s += __shfl_down_sync(0xffffffffu, s, 2);
        s += __shfl_down_sync(0xffffffffu, s, 1);
        if (l == 0) xout[b] = s + b2[0];
    }
}

// ---------------------------------------------------------------------------
// TF32 mma.sync NT GEMM: C[M,N] = relu(A[M,K] @ Bm[N,K]^T + bias[N])
// 128x128 CTA tile, 8 warps, warp 64x32. K-chunk 32, 2-stage cp.async.
// ---------------------------------------------------------------------------
template <bool ROUND_OUT>
__global__ __launch_bounds__(256) void gemm_mma(
    const float* __restrict__ A,
    const float* __restrict__ Bm,
    const float* __restrict__ bias,
    float* __restrict__ C,
    int M, int N, int K)
{
    extern __shared__ float smem[];
    constexpr int TILE = 4608;
    constexpr int STAGE = 2 * TILE;

    const int tid  = threadIdx.x;
    const int wid  = tid >> 5;
    const int lane = tid & 31;
    const int q    = lane >> 2;
    const int r    = lane & 3;
    const int wm   = (wid & 1) * 64;
    const int wn   = (wid >> 1) * 32;
    const int m0   = blockIdx.y * 128;
    const int n0   = blockIdx.x * 128;

    const uint32_t sb = smem_to_u32(smem);

    float acc[4][4][4];
    #pragma unroll
    for (int i = 0; i < 4; i++)
        #pragma unroll
        for (int j = 0; j < 4; j++)
            #pragma unroll
            for (int c = 0; c < 4; c++) acc[i][j][c] = 0.f;

    const int nK = K / 32;

    auto load_chunk = [&](int kc, int stage) {
        const uint32_t aAddr = sb + stage * STAGE * 4;
        const uint32_t bAddr = aAddr + TILE * 4;
        const int k0 = kc * 32;
        #pragma unroll
        for (int i = 0; i < 4; i++) {
            int u  = i * 256 + tid;
            int rr = u >> 3;
            int c4 = u & 7;
            uint32_t off = (uint32_t)(rr * 36 + c4 * 4) * 4;
            cp16(aAddr + off, A  + (size_t)(m0 + rr) * K + k0 + c4 * 4);
            cp16(bAddr + off, Bm + (size_t)(n0 + rr) * K + k0 + c4 * 4);
        }
        asm volatile("cp.async.commit_group;" ::: "memory");
    };

    load_chunk(0, 0);

    for (int kc = 0; kc < nK; kc++) {
        const int stage = kc & 1;
        if (kc + 1 < nK) {
            load_chunk(kc + 1, stage ^ 1);
            asm volatile("cp.async.wait_group 1;" ::: "memory");
        } else {
            asm volatile("cp.async.wait_group 0;" ::: "memory");
        }
        __syncthreads();

        const float* Ab = smem + stage * STAGE;
        const float* Bb = Ab + TILE;

        #pragma unroll
        for (int ks = 0; ks < 4; ks++) {
            const int k = ks * 8;
            uint32_t a[4][4];
            #pragma unroll
            for (int i = 0; i < 4; i++) {
                const int m = wm + 16 * i + q;
                a[i][0] = __float_as_uint(Ab[m * 36 + k + r]);
                a[i][1] = __float_as_uint(Ab[(m + 8) * 36 + k + r]);
                a[i][2] = __float_as_uint(Ab[m * 36 + k + r + 4]);
                a[i][3] = __float_as_uint(Ab[(m + 8) * 36 + k + r + 4]);
            }
            uint32_t bfr[4][2];
            #pragma unroll
            for (int j = 0; j < 4; j++) {
                const int n = wn + 8 * j + q;
                bfr[j][0] = __float_as_uint(Bb[n * 36 + k + r]);
                bfr[j][1] = __float_as_uint(Bb[n * 36 + k + r + 4]);
            }
            #pragma unroll
            for (int i = 0; i < 4; i++)
                #pragma unroll
                for (int j = 0; j < 4; j++) {
                    asm volatile(
                        "mma.sync.aligned.m16n8k8.row.col.f32.tf32.tf32.f32 "
                        "{%0,%1,%2,%3}, {%4,%5,%6,%7}, {%8,%9}, {%0,%1,%2,%3};"
                        : "+f"(acc[i][j][0]), "+f"(acc[i][j][1]),
                          "+f"(acc[i][j][2]), "+f"(acc[i][j][3])
                        : "r"(a[i][0]), "r"(a[i][1]), "r"(a[i][2]), "r"(a[i][3]),
                          "r"(bfr[j][0]), "r"(bfr[j][1]));
                }
        }
        __syncthreads();
    }

    #pragma unroll
    for (int i = 0; i < 4; i++) {
        #pragma unroll
        for (int j = 0; j < 4; j++) {
            const int row = m0 + wm + 16 * i + q;
            const int col = n0 + wn + 8 * j + 2 * r;
            const float bj0 = bias[col];
            const float bj1 = bias[col + 1];
            float v00 = fmaxf(acc[i][j][0] + bj0, 0.f);
            float v01 = fmaxf(acc[i][j][1] + bj1, 0.f);
            float v10 = fmaxf(acc[i][j][2] + bj0, 0.f);
            float v11 = fmaxf(acc[i][j][3] + bj1, 0.f);
            if (ROUND_OUT) {
                v00 = tf32r(v00); v01 = tf32r(v01);
                v10 = tf32r(v10); v11 = tf32r(v11);
            }
            float2 lo = make_float2(v00, v01);
            float2 hi = make_float2(v10, v11);
            *(float2*)(C + (size_t)row * N + col)       = lo;
            *(float2*)(C + (size_t)(row + 8) * N + col) = hi;
        }
    }
}

// ---------------------------------------------------------------------------
extern "C" void kernel_launch(void* const* d_in, const int* in_sizes, int n_in,
                              void* d_out, int out_size)
{
    const float* pov   = (const float*)d_in[0];
    const float* white = (const float*)d_in[1];
    const float* black = (const float*)d_in[2];
    const float* Ww    = (const float*)d_in[3];
    const float* bw    = (const float*)d_in[4];
    const float* Wb    = (const float*)d_in[5];
    const float* bb    = (const float*)d_in[6];
    const float* W0    = (const float*)d_in[7];
    const float* b0    = (const float*)d_in[8];
    const float* W1    = (const float*)d_in[9];
    const float* b1    = (const float*)d_in[10];
    const float* W2    = (const float*)d_in[11];
    const float* b2    = (const float*)d_in[12];
    const float* Wm0   = (const float*)d_in[13];
    const float* bm0   = (const float*)d_in[14];
    const float* Wm1   = (const float*)d_in[15];
    const float* bm1   = (const float*)d_in[16];

    const int B = in_sizes[0];
    float* out  = (float*)d_out;
    float* xout = out;                  // [B]
    float* aout = out + B;              // [B, MOVE_N]

    float *wwT_ptr, *wbT_ptr, *base_ptr, *hidden_ptr;
    float *wm0r_ptr, *wm1r_ptr, *w0t_ptr, *w1t_ptr, *w2r_ptr;
    int* cnt_ptr;
    cudaGetSymbolAddress((void**)&wwT_ptr,    g_WwT);
    cudaGetSymbolAddress((void**)&wbT_ptr,    g_WbT);
    cudaGetSymbolAddress((void**)&base_ptr,   g_base);
    cudaGetSymbolAddress((void**)&hidden_ptr, g_hidden);
    cudaGetSymbolAddress((void**)&wm0r_ptr,   g_Wm0r);
    cudaGetSymbolAddress((void**)&wm1r_ptr,   g_Wm1r);
    cudaGetSymbolAddress((void**)&w0t_ptr,    g_W0t);
    cudaGetSymbolAddress((void**)&w1t_ptr,    g_W1t);
    cudaGetSymbolAddress((void**)&w2r_ptr,    g_W2r);
    cudaGetSymbolAddress((void**)&cnt_ptr,    g_cnt);

    static bool init_done = false;
    static cudaStream_t side = nullptr;
    static cudaEvent_t evFork = nullptr, evJoin = nullptr;
    if (!init_done) {
        cudaFuncSetAttribute(gemm_mma<true>,
            cudaFuncAttributeMaxDynamicSharedMemorySize, 73728);
        cudaFuncSetAttribute(gemm_mma<false>,
            cudaFuncAttributeMaxDynamicSharedMemorySize, 73728);
        cudaStreamCreateWithFlags(&side, cudaStreamNonBlocking);
        cudaEventCreateWithFlags(&evFork, cudaEventDisableTiming);
        cudaEventCreateWithFlags(&evJoin, cudaEventDisableTiming);
        init_done = true;
    }

    // ---- fork: side stream runs weight prep concurrent with the scan ----
    cudaEventRecord(evFork, 0);
    cudaStreamWaitEvent(side, evFork, 0);

    // main stream: counters + the 1.34 GB multihot scan (long pole)
    cudaMemsetAsync(cnt_ptr, 0, 2 * BATCH_MAX * sizeof(int));
    {
        const int nchunks = B * HALF_KP4 / 256;
        scan_kernel<<<1184, 256>>>((const uint4*)white, (const uint4*)black,
                                   nchunks);
    }

    // side stream: table transposes + weight rounding
    {
        dim3 grid(HALF_KP / 32, 256 / 32, 2);
        dim3 blk(32, 8);
        transpose_kernel<<<grid, blk, 0, side>>>(Ww, wwT_ptr, Wb, wbT_ptr);
        round_all_kernel<<<1152, 256, 0, side>>>(Wm0, wm0r_ptr, Wm1, wm1r_ptr);
        round_heads_kernel<<<69, 256, 0, side>>>(W0, w0t_ptr, W1, w1t_ptr,
                                                 W2, w2r_ptr);
    }

    // ---- join: gather needs scan + transposes + head weights ----
    cudaEventRecord(evJoin, side);
    cudaStreamWaitEvent(0, evJoin, 0);

    // gather + value head: one warp per position
    gather_kernel<<<B / 8, 256>>>(pov, wwT_ptr, bw, wbT_ptr, bb,
                                  w0t_ptr, b0, w1t_ptr, b1, w2r_ptr, b2, xout);

    // hidden = tf32r(relu(base @ Wm0^T + bm0))   M=B, N=256, K=512
    {
        dim3 grid(256 / 128, B / 128);
        gemm_mma<true><<<grid, 256, 73728>>>(base_ptr, wm0r_ptr, bm0,
                                             hidden_ptr, B, 256, 512);
    }
    // a = relu(hidden @ Wm1^T + bm1)             M=B, N=4096, K=256
    {
        dim3 grid(MOVE_N / 128, B / 128);
        gemm_mma<false><<<grid, 256, 73728>>>(hidden_ptr, wm1r_ptr, bm1,
                                              aout, B, MOVE_N, 256);
    }
}